// round 15
// baseline (speedup 1.0000x reference)
#include <cuda_runtime.h>
#include <cuda_bf16.h>
#include <math.h>
#include <stdint.h>

#define B_  64
#define U_  256
#define MAT (U_*U_)
#define BM_ (B_*MAT)
#define KC   64
#define NCH  (U_/KC)
#define SPAD 72                    // chunk row pad (bf16)
#define TPAD 264                   // T-strip row pad (bf16)
#define ST_ELE ((128 + 256) * SPAD)
#define TS_OFF (2*ST_ELE)
#define SM_ELE (TS_OFF + 128*TPAD)
#define SM_DYN (SM_ELE*2)

// ---------------- scratch (__device__ globals; device-side access only) ----------------
__device__ __align__(16) __nv_bfloat16 g_Sb [BM_];
__device__ __align__(16) __nv_bfloat16 g_Wtz[MAT];
__device__ __align__(16) __nv_bfloat16 g_Wtr[MAT];
__device__ __align__(16) __nv_bfloat16 g_Wth[MAT];
__device__ __align__(16) __nv_bfloat16 g_sgb[BM_];
__device__ __align__(16) __nv_bfloat16 g_Szb[BM_];   // Sigma_out_z bf16 off-diag
__device__ float g_dz[B_*U_];                        // fp32 diag of Sigma_out_z
__device__ float g_dg[B_*U_];                        // fp32 diag of sigma_g
__device__ float g_z [B_*U_], g_gz[B_*U_], g_r [B_*U_], g_gr[B_*U_];
__device__ float g_h [B_*U_], g_gh[B_*U_];
__device__ float g_gi[B_*U_], g_ahx[B_*U_];
__device__ float g_nx[B_], g_np[B_], g_ngin[B_], g_trS[B_];

__device__ __forceinline__ float splus(float x) { return log1pf(expf(x)); }

__device__ __forceinline__ uint32_t smem_u32(const void* p) {
    uint32_t a;
    asm("{ .reg .u64 t; cvta.to.shared.u64 t, %1; cvt.u32.u64 %0, t; }" : "=r"(a) : "l"(p));
    return a;
}
__device__ __forceinline__ uint32_t pack_bf2(float lo, float hi) {
    __nv_bfloat162 v = __floats2bfloat162_rn(lo, hi);
    return *(uint32_t*)&v;
}
__device__ __forceinline__ float2 unpack_bf2(uint32_t u) {
    return __bfloat1622float2(*(__nv_bfloat162*)&u);
}
__device__ __forceinline__ void ldsm_x4(uint32_t* r, uint32_t addr) {
    asm volatile("ldmatrix.sync.aligned.m8n8.x4.shared.b16 {%0,%1,%2,%3}, [%4];"
        : "=r"(r[0]), "=r"(r[1]), "=r"(r[2]), "=r"(r[3]) : "r"(addr));
}
__device__ __forceinline__ void mma16816(float* c, const uint32_t* a, const uint32_t* b) {
    asm volatile("mma.sync.aligned.m16n8k16.row.col.f32.bf16.bf16.f32 "
        "{%0,%1,%2,%3}, {%4,%5,%6,%7}, {%8,%9}, {%0,%1,%2,%3};"
        : "+f"(c[0]), "+f"(c[1]), "+f"(c[2]), "+f"(c[3])
        : "r"(a[0]), "r"(a[1]), "r"(a[2]), "r"(a[3]), "r"(b[0]), "r"(b[1]));
}
__device__ __forceinline__ void cpa16(uint32_t dst, const void* src) {
    asm volatile("cp.async.cg.shared.global [%0], [%1], 16;" :: "r"(dst), "l"(src));
}
#define CPA_COMMIT() asm volatile("cp.async.commit_group;" ::: "memory")
#define CPA_WAIT1()  asm volatile("cp.async.wait_group 1;" ::: "memory")
#define CPA_WAIT0()  asm volatile("cp.async.wait_group 0;" ::: "memory")

// ---------------- fused prep: gates pass 1 FIRST, then transW, then convS ----------------
// bids [0,192): gate GEMVs (slow, launch first) ; [192,384): transW ; [384,2432): convS
__global__ void __launch_bounds__(256)
prep_kernel(const float* __restrict__ S,
            const float* __restrict__ Wz, const float* __restrict__ Wr,
            const float* __restrict__ Wh,
            const float* __restrict__ x, const float* __restrict__ prev,
            const float* __restrict__ Uz, const float* __restrict__ Ur,
            const float* __restrict__ Uh)
{
    const int bid = blockIdx.x, tid = threadIdx.x;

    if (bid < 192) {        // ---- gates pass 1 (slice 0 = z, 1 = r, 2 = h_x + scalars) ----
        __shared__ float xs[U_], ps[U_];
        __shared__ float4 sred[256];
        __shared__ float part[8][3];
        const int slice = bid / 64;
        const int b = bid & 63;
        const int lane = tid & 31, wd = tid >> 5;
        xs[tid] = x[b*U_ + tid];
        ps[tid] = prev[b*U_ + tid];
        __syncthreads();

        const int kt = tid >> 6, ut = tid & 63;
        const int u4 = ut << 2;
        const int k0 = kt * 64;
        float a0 = 0.f, a1 = 0.f, a2 = 0.f, a3 = 0.f;

        if (slice < 2) {
            const float* Ug = slice ? Ur : Uz;
            const float* Wg = slice ? Wr : Wz;
#pragma unroll 4
            for (int kk = 0; kk < 64; kk++) {
                const int k = k0 + kk;
                const float4 av = *(const float4*)(Ug + k*U_ + u4);
                const float4 wv = *(const float4*)(Wg + k*U_ + u4);
                const float xv = xs[k], pv = ps[k];
                a0 = fmaf(xv, av.x, fmaf(pv, wv.x, a0));
                a1 = fmaf(xv, av.y, fmaf(pv, wv.y, a1));
                a2 = fmaf(xv, av.z, fmaf(pv, wv.z, a2));
                a3 = fmaf(xv, av.w, fmaf(pv, wv.w, a3));
            }
        } else {
#pragma unroll 8
            for (int kk = 0; kk < 64; kk++) {
                const int k = k0 + kk;
                const float4 av = *(const float4*)(Uh + k*U_ + u4);
                const float xv = xs[k];
                a0 = fmaf(xv, av.x, a0);
                a1 = fmaf(xv, av.y, a1);
                a2 = fmaf(xv, av.z, a2);
                a3 = fmaf(xv, av.w, a3);
            }
        }
        sred[tid] = make_float4(a0, a1, a2, a3);
        __syncthreads();

        if (kt == 0) {
            const float4 r0 = sred[ut], r1 = sred[64 + ut], r2 = sred[128 + ut], r3 = sred[192 + ut];
            float v[4] = { r0.x + r1.x + r2.x + r3.x, r0.y + r1.y + r2.y + r3.y,
                           r0.z + r1.z + r2.z + r3.z, r0.w + r1.w + r2.w + r3.w };
            if (slice == 0) {
#pragma unroll
                for (int j = 0; j < 4; j++) {
                    const float z = 1.f / (1.f + expf(-v[j]));
                    g_z [b*U_ + u4 + j] = z;
                    g_gz[b*U_ + u4 + j] = z * (1.f - z);
                }
            } else if (slice == 1) {
#pragma unroll
                for (int j = 0; j < 4; j++) {
                    const float r = 1.f / (1.f + expf(-v[j]));
                    g_r [b*U_ + u4 + j] = r;
                    g_gr[b*U_ + u4 + j] = r * (1.f - r);
                    g_gi[b*U_ + u4 + j] = ps[u4 + j] * r;
                }
            } else {
#pragma unroll
                for (int j = 0; j < 4; j++) g_ahx[b*U_ + u4 + j] = v[j];
            }
        }

        if (slice == 2) {
            float v0 = xs[tid]*xs[tid], v1 = ps[tid]*ps[tid], v2 = S[b*MAT + tid*(U_+1)];
#pragma unroll
            for (int off = 16; off > 0; off >>= 1) {
                v0 += __shfl_down_sync(0xFFFFFFFFu, v0, off);
                v1 += __shfl_down_sync(0xFFFFFFFFu, v1, off);
                v2 += __shfl_down_sync(0xFFFFFFFFu, v2, off);
            }
            if (lane == 0) { part[wd][0] = v0; part[wd][1] = v1; part[wd][2] = v2; }
            __syncthreads();
            if (tid == 0) {
                float s0 = 0.f, s1 = 0.f, s2 = 0.f;
#pragma unroll
                for (int w = 0; w < 8; w++) { s0 += part[w][0]; s1 += part[w][1]; s2 += part[w][2]; }
                g_nx[b] = s0; g_np[b] = s1; g_trS[b] = s2;
            }
        }
        return;
    }

    if (bid < 384) {                                   // ---- transW (192 blocks) ----
        __shared__ float tile[32][33];
        const int k = bid - 192;
        const int gidx = k >> 6, sub = k & 63;
        const float* W = (gidx == 0) ? Wz : (gidx == 1) ? Wr : Wh;
        __nv_bfloat16* Wt = (gidx == 0) ? g_Wtz : (gidx == 1) ? g_Wtr : g_Wth;
        const int m0 = (sub >> 3) * 32, i0 = (sub & 7) * 32;
        const int tx = tid & 31, ty = tid >> 5;
#pragma unroll
        for (int q = 0; q < 4; q++)
            tile[ty*4 + q][tx] = W[(m0 + ty*4 + q) * U_ + i0 + tx];
        __syncthreads();
#pragma unroll
        for (int q = 0; q < 4; q++)
            Wt[(i0 + ty*4 + q) * U_ + m0 + tx] = __float2bfloat16_rn(tile[tx][ty*4 + q]);
        return;
    }

    // ---- convS (2048 blocks) ----
    {
        const int base = ((bid - 384) * 256 + tid) * 8;
        float4 f0 = *(const float4*)(S + base);
        float4 f1 = *(const float4*)(S + base + 4);
        uint4 o;
        o.x = pack_bf2(f0.x, f0.y); o.y = pack_bf2(f0.z, f0.w);
        o.z = pack_bf2(f1.x, f1.y); o.w = pack_bf2(f1.z, f1.w);
        *(uint4*)(g_Sb + base) = o;
    }
}

// ---------------- fused T+Q kernel (gates2 folded into HP0 x==0 CTAs) --------
template<int HP>
__global__ void __launch_bounds__(512, 1)
tq_phase(const float* __restrict__ Sst, const float* __restrict__ prev,
         const float* __restrict__ ws0, const float* __restrict__ us0,
         const float* __restrict__ ws1, const float* __restrict__ us1,
         const float* __restrict__ Whf, float* __restrict__ mu_out,
         float* __restrict__ outp)
{
    extern __shared__ __nv_bfloat16 sm[];
    __shared__ float tpart[16];
    __shared__ float strg;

    const int tid = threadIdx.x, lane = tid & 31, wid = tid >> 5;
    const int mt   = blockIdx.x & 1;
    const int gate = (HP == 0) ? (blockIdx.x >> 1) : 0;
    const int b = blockIdx.y;
    const int i0 = mt * 128;

    // ---- folded gates pass 2 (HP0, blockIdx.x==0 only)
    if (HP == 0 && blockIdx.x == 0) {
        float* sf = (float*)sm;
        if (tid < 256) sf[tid] = g_gi[b*U_ + tid];
        __syncthreads();
        if (tid < 256) {
            const int kt = tid >> 6, ut = tid & 63;
            const int u4 = ut << 2, k0 = kt * 64;
            float a0 = 0.f, a1 = 0.f, a2 = 0.f, a3 = 0.f;
#pragma unroll 8
            for (int kk = 0; kk < 64; kk++) {
                const int k = k0 + kk;
                const float4 wv = *(const float4*)(Whf + k*U_ + u4);
                const float gv = sf[k];
                a0 = fmaf(gv, wv.x, a0);
                a1 = fmaf(gv, wv.y, a1);
                a2 = fmaf(gv, wv.z, a2);
                a3 = fmaf(gv, wv.w, a3);
            }
            ((float4*)(sf + 256))[tid] = make_float4(a0, a1, a2, a3);
        }
        __syncthreads();
        if (tid < 64) {
            const float4* sr4 = (const float4*)(sf + 256);
            const float4 r0 = sr4[tid], r1 = sr4[64 + tid], r2 = sr4[128 + tid], r3 = sr4[192 + tid];
            float v[4] = { r0.x + r1.x + r2.x + r3.x, r0.y + r1.y + r2.y + r3.y,
                           r0.z + r1.z + r2.z + r3.z, r0.w + r1.w + r2.w + r3.w };
            const int u4 = tid << 2;
#pragma unroll
            for (int j = 0; j < 4; j++) {
                const int u = u4 + j;
                const float ah = g_ahx[b*U_ + u] + v[j];
                const float h = tanhf(ah);
                g_h [b*U_ + u] = h;
                g_gh[b*U_ + u] = 1.f - h*h;
                const float z = g_z[b*U_ + u];
                mu_out[b*U_ + u] = z * prev[b*U_ + u] + (1.f - z) * h;
            }
        }
        if (tid < 256) {
            float v0 = sf[tid] * sf[tid];
#pragma unroll
            for (int off = 16; off > 0; off >>= 1)
                v0 += __shfl_down_sync(0xFFFFFFFFu, v0, off);
            if (lane == 0) tpart[wid] = v0;
        }
        __syncthreads();
        if (tid == 0) {
            float s = 0.f;
#pragma unroll
            for (int w = 0; w < 8; w++) s += tpart[w];
            g_ngin[b] = s;
        }
        __syncthreads();
    }

    float trg = 0.f;
    if (HP == 1) {
        float tv = (tid < U_) ? g_dg[b*U_ + tid] : 0.f;
#pragma unroll
        for (int off = 16; off > 0; off >>= 1)
            tv += __shfl_down_sync(0xFFFFFFFFu, tv, off);
        if (lane == 0) tpart[wid] = tv;
        __syncthreads();
        if (tid == 0) {
            float s = 0.f;
#pragma unroll
            for (int w = 0; w < 16; w++) s += tpart[w];
            strg = s;
        }
        __syncthreads();
        trg = strg;
    }

    const __nv_bfloat16* Wt = (HP == 1) ? g_Wth : (gate ? g_Wtr : g_Wtz);
    const __nv_bfloat16* Bmat = (HP == 1) ? (g_sgb + b*MAT) : (g_Sb + b*MAT);
    const __nv_bfloat16* Astrip = Wt + i0*U_;

    const uint32_t smb = smem_u32(sm);
    const uint32_t tsb = smb + (uint32_t)(TS_OFF * 2);

    const int lr = tid >> 3, lc = (tid & 7) << 3;

    auto load1 = [&](int st, int ch) {
        const uint32_t dA = smb + (uint32_t)((st*ST_ELE) * 2);
        const uint32_t dB = dA + (uint32_t)((128*SPAD) * 2);
        const int kb = ch * KC;
#pragma unroll
        for (int i = 0; i < 2; i++) {
            const int r = lr + i*64;
            cpa16(dA + (uint32_t)((r*SPAD + lc) * 2), Astrip + r*U_ + kb + lc);
        }
#pragma unroll
        for (int i = 0; i < 4; i++) {
            const int r = lr + i*64;
            cpa16(dB + (uint32_t)((r*SPAD + lc) * 2), Bmat + r*U_ + kb + lc);
        }
        CPA_COMMIT();
    };
    auto load2 = [&](int st, int ch) {
        const uint32_t dB = smb + (uint32_t)((st*ST_ELE) * 2);
        const int kb = ch * KC;
#pragma unroll
        for (int i = 0; i < 4; i++) {
            const int r = lr + i*64;
            cpa16(dB + (uint32_t)((r*SPAD + lc) * 2), Wt + r*U_ + kb + lc);
        }
        CPA_COMMIT();
    };

    const int warp_m = wid & 3, warp_n = wid >> 2;
    const int arow = (lane & 7) | (((lane >> 3) & 1) << 3);
    const int akof = (lane >> 4) << 3;
    const int bxrow = (lane & 7) + ((lane >> 4) << 3);
    const int bxkof = ((lane >> 3) & 1) << 3;
    const int rb = lane >> 2;
    const int cb = (lane & 3) << 1;
    const int jbase = warp_n * 64;

    float acc[2][8][4];

    // ===== step 1: T strip =====
#pragma unroll
    for (int ms = 0; ms < 2; ms++)
#pragma unroll
        for (int ns = 0; ns < 8; ns++)
#pragma unroll
            for (int q = 0; q < 4; q++) acc[ms][ns][q] = 0.f;

    load1(0, 0);
    load1(1, 1);
    for (int ch = 0; ch < NCH; ch++) {
        if (ch < NCH - 1) { CPA_WAIT1(); } else { CPA_WAIT0(); }
        __syncthreads();
        const int st = ch & 1;
        const uint32_t baseA = smb + (uint32_t)((st*ST_ELE) * 2);
        const uint32_t baseB = baseA + (uint32_t)((128*SPAD) * 2);
#pragma unroll
        for (int ks = 0; ks < KC/16; ks++) {
            const int k0 = ks * 16;
            uint32_t af[2][4];
#pragma unroll
            for (int ms = 0; ms < 2; ms++)
                ldsm_x4(af[ms], baseA + (uint32_t)(((warp_m*32 + ms*16 + arow)*SPAD + k0 + akof) * 2));
            uint32_t bf[8][2];
#pragma unroll
            for (int ns2 = 0; ns2 < 4; ns2++) {
                uint32_t q4[4];
                ldsm_x4(q4, baseB + (uint32_t)(((jbase + ns2*16 + bxrow)*SPAD + k0 + bxkof) * 2));
                bf[ns2*2][0]   = q4[0]; bf[ns2*2][1]   = q4[1];
                bf[ns2*2+1][0] = q4[2]; bf[ns2*2+1][1] = q4[3];
            }
#pragma unroll
            for (int ms = 0; ms < 2; ms++)
#pragma unroll
                for (int ns = 0; ns < 8; ns++)
                    mma16816(acc[ms][ns], af[ms], bf[ns]);
        }
        __syncthreads();
        if (ch + 2 < NCH) load1(st, ch + 2);
    }

#pragma unroll
    for (int ms = 0; ms < 2; ms++)
#pragma unroll
        for (int hh = 0; hh < 2; hh++) {
            const int rowl = warp_m*32 + ms*16 + hh*8 + rb;
#pragma unroll
            for (int ns = 0; ns < 8; ns++) {
                const int coll = jbase + ns*8 + cb;
                *(uint32_t*)((char*)sm + (TS_OFF + rowl*TPAD + coll)*2)
                    = pack_bf2(acc[ms][ns][hh*2], acc[ms][ns][hh*2 + 1]);
            }
        }
    __syncthreads();

    // ===== step 2: Q strip =====
#pragma unroll
    for (int ms = 0; ms < 2; ms++)
#pragma unroll
        for (int ns = 0; ns < 8; ns++)
#pragma unroll
            for (int q = 0; q < 4; q++) acc[ms][ns][q] = 0.f;

    load2(0, 0);
    load2(1, 1);
    for (int ch = 0; ch < NCH; ch++) {
        if (ch < NCH - 1) { CPA_WAIT1(); } else { CPA_WAIT0(); }
        __syncthreads();
        const int st = ch & 1;
        const uint32_t baseB = smb + (uint32_t)((st*ST_ELE) * 2);
        const int kb = ch * KC;
#pragma unroll
        for (int ks = 0; ks < KC/16; ks++) {
            const int k0 = ks * 16;
            uint32_t af[2][4];
#pragma unroll
            for (int ms = 0; ms < 2; ms++)
                ldsm_x4(af[ms], tsb + (uint32_t)(((warp_m*32 + ms*16 + arow)*TPAD + kb + k0 + akof) * 2));
            uint32_t bf[8][2];
#pragma unroll
            for (int ns2 = 0; ns2 < 4; ns2++) {
                uint32_t q4[4];
                ldsm_x4(q4, baseB + (uint32_t)(((jbase + ns2*16 + bxrow)*SPAD + k0 + bxkof) * 2));
                bf[ns2*2][0]   = q4[0]; bf[ns2*2][1]   = q4[1];
                bf[ns2*2+1][0] = q4[2]; bf[ns2*2+1][1] = q4[3];
            }
#pragma unroll
            for (int ms = 0; ms < 2; ms++)
#pragma unroll
                for (int ns = 0; ns < 8; ns++)
                    mma16816(acc[ms][ns], af[ms], bf[ns]);
        }
        __syncthreads();
        if (ch + 2 < NCH) load2(st, ch + 2);
    }

    // ===== fused epilogues =====
    if (HP == 0 && gate == 0) {                    // Sigma_out_z: bf16 + fp32 diag
        const float nx = g_nx[b], sc = g_np[b] + g_trS[b];
        float2 gzj[8];
#pragma unroll
        for (int ns = 0; ns < 8; ns++)
            gzj[ns] = *(const float2*)(g_gz + b*U_ + jbase + ns*8 + cb);
#pragma unroll
        for (int ms = 0; ms < 2; ms++)
#pragma unroll
            for (int hh = 0; hh < 2; hh++) {
                const int row = i0 + warp_m*32 + ms*16 + hh*8 + rb;
                const float dadd = sc * splus(ws0[row]) + nx * splus(us0[row]);
                const float gzi = g_gz[b*U_ + row];
                __nv_bfloat16* dstr = g_Szb + b*MAT + row*U_;
#pragma unroll
                for (int ns = 0; ns < 8; ns++) {
                    const int colg = jbase + ns*8 + cb;
                    float v0 = acc[ms][ns][hh*2], v1 = acc[ms][ns][hh*2 + 1];
                    if (colg == row)     v0 += dadd;
                    if (colg + 1 == row) v1 += dadd;
                    const float o0 = v0 * gzi * gzj[ns].x;
                    const float o1 = v1 * gzi * gzj[ns].y;
                    if (colg == row)     g_dz[b*U_ + row] = o0;
                    if (colg + 1 == row) g_dz[b*U_ + row] = o1;
                    *(uint32_t*)(dstr + colg) = pack_bf2(o0, o1);
                }
            }
    }
    else if (HP == 0) {                            // sigma_g (bf16 + fp32 diag)
        const float nx = g_nx[b], sc = g_np[b] + g_trS[b];
        float2 grj[8], rj[8], pj[8];
#pragma unroll
        for (int ns = 0; ns < 8; ns++) {
            const int cg = jbase + ns*8 + cb;
            grj[ns] = *(const float2*)(g_gr + b*U_ + cg);
            rj[ns]  = *(const float2*)(g_r  + b*U_ + cg);
            pj[ns]  = *(const float2*)(prev + b*U_ + cg);
        }
#pragma unroll
        for (int ms = 0; ms < 2; ms++)
#pragma unroll
            for (int hh = 0; hh < 2; hh++) {
                const int row = i0 + warp_m*32 + ms*16 + hh*8 + rb;
                const float dadd = sc * splus(ws1[row]) + nx * splus(us1[row]);
                const float gri = g_gr[b*U_ + row];
                const float ri  = g_r [b*U_ + row];
                const float pi  = prev[b*U_ + row];
                const float* Srow = Sst + b*MAT + row*U_;
                __nv_bfloat16* dstr = g_sgb + b*MAT + row*U_;
#pragma unroll
                for (int ns = 0; ns < 8; ns++) {
                    const int colg = jbase + ns*8 + cb;
                    float v0 = acc[ms][ns][hh*2], v1 = acc[ms][ns][hh*2 + 1];
                    if (colg == row)     v0 += dadd;
                    if (colg + 1 == row) v1 += dadd;
                    const float2 Sv = *(const float2*)(Srow + colg);
                    const float sr0 = v0 * gri * grj[ns].x;
                    const float sr1 = v1 * gri * grj[ns].y;
                    const float res0 = Sv.x*sr0 + pi*pj[ns].x*sr0 + ri*rj[ns].x*Sv.x;
                    const float res1 = Sv.y*sr1 + pi*pj[ns].y*sr1 + ri*rj[ns].y*Sv.y;
                    if (colg == row)     g_dg[b*U_ + row] = res0;
                    if (colg + 1 == row) g_dg[b*U_ + row] = res1;
                    *(uint32_t*)(dstr + colg) = pack_bf2(res0, res1);
                }
            }
    }
    else {                                         // HP 1: final Sigma_out
        const float nx = g_nx[b], sc = g_ngin[b] + trg;
        float2 ghj[8], zj[8], hj[8], pj[8];
#pragma unroll
        for (int ns = 0; ns < 8; ns++) {
            const int cg = jbase + ns*8 + cb;
            ghj[ns] = *(const float2*)(g_gh + b*U_ + cg);
            zj[ns]  = *(const float2*)(g_z  + b*U_ + cg);
            hj[ns]  = *(const float2*)(g_h  + b*U_ + cg);
            pj[ns]  = *(const float2*)(prev + b*U_ + cg);
        }
#pragma unroll
        for (int ms = 0; ms < 2; ms++)
#pragma unroll
            for (int hh = 0; hh < 2; hh++) {
                const int row = i0 + warp_m*32 + ms*16 + hh*8 + rb;
                const float dadd = sc * splus(ws0[row]) + nx * splus(us0[row]);
                const float ghi = g_gh[b*U_ + row];
                const float zi  = g_z [b*U_ + row];
                const float hi  = g_h [b*U_ + row];
                const float pi  = prev[b*U_ + row];
                const float dzi = g_dz[b*U_ + row];
                const __nv_bfloat16* Szrow = g_Szb + b*MAT + row*U_;
                const float* Srow  = Sst  + b*MAT + row*U_;
                float* dstr = outp + b*MAT + row*U_;
#pragma unroll
                for (int ns = 0; ns < 8; ns++) {
                    const int colg = jbase + ns*8 + cb;
                    float v0 = acc[ms][ns][hh*2], v1 = acc[ms][ns][hh*2 + 1];
                    if (colg == row)     v0 += dadd;
                    if (colg + 1 == row) v1 += dadd;
                    const float2 Szv = unpack_bf2(*(const uint32_t*)(Szrow + colg));
                    const float2 Ssv = *(const float2*)(Srow + colg);
                    float2 o;
#pragma unroll
                    for (int e = 0; e < 2; e++) {
                        const int j = colg + e;
                        const float q  = (e == 0) ? v0 : v1;
                        float Sz = (e == 0) ? Szv.x : Szv.y;
                        if (j == row) Sz = dzi;
                        const float Ss = (e == 0) ? Ssv.x : Ssv.y;
                        const float zjv = (e == 0) ? zj[ns].x : zj[ns].y;
                        const float hjv = (e == 0) ? hj[ns].x : hj[ns].y;
                        const float pjv = (e == 0) ? pj[ns].x : pj[ns].y;
                        const float Sh = q * ghi * ((e == 0) ? ghj[ns].x : ghj[ns].y);
                        float oo = Sz*Ss + zi*zjv*Ss + pi*pjv*Sz
                                 + Sz*Sh + (1.f - zi)*(1.f - zjv)*Sh + hi*hjv*Sz
                                 - Sz*(pi*hjv + hi*pjv);
                        const unsigned bits = __float_as_uint(oo);
                        if (((bits >> 23) & 255u) == 255u) oo = 0.f;
                        if (j == row) oo = fabsf(oo);
                        (e == 0 ? o.x : o.y) = oo;
                    }
                    *(float2*)(dstr + colg) = o;
                }
            }
    }
}

// ---------------- launch ----------------
extern "C" void kernel_launch(void* const* d_in, const int* in_sizes, int n_in,
                              void* d_out, int out_size)
{
    const float* x    = (const float*)d_in[0];
    const float* prev = (const float*)d_in[1];
    const float* S    = (const float*)d_in[2];
    const float* Uz   = (const float*)d_in[3];
    const float* uzs  = (const float*)d_in[4];
    const float* Wz   = (const float*)d_in[5];
    const float* wzs  = (const float*)d_in[6];
    const float* Ur   = (const float*)d_in[7];
    const float* urs  = (const float*)d_in[8];
    const float* Wr   = (const float*)d_in[9];
    const float* wrs  = (const float*)d_in[10];
    const float* Uh   = (const float*)d_in[11];
    const float* uhs  = (const float*)d_in[12];
    const float* Wh   = (const float*)d_in[13];
    const float* whs  = (const float*)d_in[14];
    float* out = (float*)d_out;

    cudaFuncSetAttribute(tq_phase<0>, cudaFuncAttributeMaxDynamicSharedMemorySize, SM_DYN);
    cudaFuncSetAttribute(tq_phase<1>, cudaFuncAttributeMaxDynamicSharedMemorySize, SM_DYN);

    prep_kernel<<<2432, 256>>>(S, Wz, Wr, Wh, x, prev, Uz, Ur, Uh);

    float* sig_out = out + B_*U_;
    tq_phase<0><<<dim3(4, 64), 512, SM_DYN>>>(S, prev, wzs, uzs, wrs, urs, Wh, out, sig_out);
    tq_phase<1><<<dim3(2, 64), 512, SM_DYN>>>(S, prev, whs, uhs, whs, uhs, Wh, out, sig_out);
}

// round 16
// speedup vs baseline: 1.0210x; 1.0210x over previous
#include <cuda_runtime.h>
#include <cuda_bf16.h>
#include <math.h>
#include <stdint.h>

#define B_  64
#define U_  256
#define MAT (U_*U_)
#define BM_ (B_*MAT)
#define KC   64
#define NCH  (U_/KC)
#define SPAD 72                    // chunk row pad (bf16)
#define TPAD 264                   // T-strip row pad (bf16)
#define ST_ELE ((128 + 256) * SPAD)
#define TS_OFF (2*ST_ELE)
#define SM_ELE (TS_OFF + 128*TPAD)
#define SM_DYN (SM_ELE*2)

// ---------------- scratch (__device__ globals; device-side access only) ----------------
__device__ __align__(16) __nv_bfloat16 g_Sb [BM_];
__device__ __align__(16) __nv_bfloat16 g_Wtz[MAT];
__device__ __align__(16) __nv_bfloat16 g_Wtr[MAT];
__device__ __align__(16) __nv_bfloat16 g_Wth[MAT];
__device__ __align__(16) __nv_bfloat16 g_sgb[BM_];
__device__ __align__(16) __nv_bfloat16 g_Szb[BM_];   // Sigma_out_z bf16 off-diag
__device__ float g_dz[B_*U_];                        // fp32 diag of Sigma_out_z
__device__ float g_dg[B_*U_];                        // fp32 diag of sigma_g
__device__ float g_z [B_*U_], g_gz[B_*U_], g_r [B_*U_], g_gr[B_*U_];
__device__ float g_h [B_*U_], g_gh[B_*U_];
__device__ float g_gi[B_*U_], g_ahx[B_*U_];
__device__ float g_nx[B_], g_np[B_], g_ngin[B_], g_trS[B_];

__device__ __forceinline__ float splus(float x) { return log1pf(expf(x)); }

__device__ __forceinline__ uint32_t smem_u32(const void* p) {
    uint32_t a;
    asm("{ .reg .u64 t; cvta.to.shared.u64 t, %1; cvt.u32.u64 %0, t; }" : "=r"(a) : "l"(p));
    return a;
}
__device__ __forceinline__ uint32_t pack_bf2(float lo, float hi) {
    __nv_bfloat162 v = __floats2bfloat162_rn(lo, hi);
    return *(uint32_t*)&v;
}
__device__ __forceinline__ float2 unpack_bf2(uint32_t u) {
    return __bfloat1622float2(*(__nv_bfloat162*)&u);
}
__device__ __forceinline__ void ldsm_x4(uint32_t* r, uint32_t addr) {
    asm volatile("ldmatrix.sync.aligned.m8n8.x4.shared.b16 {%0,%1,%2,%3}, [%4];"
        : "=r"(r[0]), "=r"(r[1]), "=r"(r[2]), "=r"(r[3]) : "r"(addr));
}
__device__ __forceinline__ void mma16816(float* c, const uint32_t* a, const uint32_t* b) {
    asm volatile("mma.sync.aligned.m16n8k16.row.col.f32.bf16.bf16.f32 "
        "{%0,%1,%2,%3}, {%4,%5,%6,%7}, {%8,%9}, {%0,%1,%2,%3};"
        : "+f"(c[0]), "+f"(c[1]), "+f"(c[2]), "+f"(c[3])
        : "r"(a[0]), "r"(a[1]), "r"(a[2]), "r"(a[3]), "r"(b[0]), "r"(b[1]));
}
__device__ __forceinline__ void cpa16(uint32_t dst, const void* src) {
    asm volatile("cp.async.cg.shared.global [%0], [%1], 16;" :: "r"(dst), "l"(src));
}
#define CPA_COMMIT() asm volatile("cp.async.commit_group;" ::: "memory")
#define CPA_WAIT1()  asm volatile("cp.async.wait_group 1;" ::: "memory")
#define CPA_WAIT0()  asm volatile("cp.async.wait_group 0;" ::: "memory")

// ---------------- fused prep: gates pass 1 (reg-staged) | transW | convS ----------------
// bids [0,192): gate GEMVs ; [192,384): transW ; [384,2432): convS
__global__ void __launch_bounds__(256)
prep_kernel(const float* __restrict__ S,
            const float* __restrict__ Wz, const float* __restrict__ Wr,
            const float* __restrict__ Wh,
            const float* __restrict__ x, const float* __restrict__ prev,
            const float* __restrict__ Uz, const float* __restrict__ Ur,
            const float* __restrict__ Uh)
{
    const int bid = blockIdx.x, tid = threadIdx.x;

    if (bid < 192) {        // ---- gates pass 1 (slice 0 = z, 1 = r, 2 = h_x + scalars) ----
        __shared__ float xs[U_], ps[U_];
        __shared__ float4 sred[256];
        __shared__ float part[8][3];
        const int slice = bid / 64;
        const int b = bid & 63;
        const int lane = tid & 31, wd = tid >> 5;
        xs[tid] = x[b*U_ + tid];
        ps[tid] = prev[b*U_ + tid];
        __syncthreads();

        const int kt = tid >> 6, ut = tid & 63;
        const int u4 = ut << 2;
        const int k0 = kt * 64;
        float a0 = 0.f, a1 = 0.f, a2 = 0.f, a3 = 0.f;

        if (slice < 2) {
            const float* Ug = slice ? Ur : Uz;
            const float* Wg = slice ? Wr : Wz;
#pragma unroll 1
            for (int c = 0; c < 8; c++) {
                const int kb = k0 + c*8;
                float4 bA[8], bW[8];
#pragma unroll
                for (int j = 0; j < 8; j++) {
                    bA[j] = *(const float4*)(Ug + (kb + j)*U_ + u4);
                    bW[j] = *(const float4*)(Wg + (kb + j)*U_ + u4);
                }
#pragma unroll
                for (int j = 0; j < 8; j++) {
                    const float xv = xs[kb + j], pv = ps[kb + j];
                    a0 = fmaf(xv, bA[j].x, fmaf(pv, bW[j].x, a0));
                    a1 = fmaf(xv, bA[j].y, fmaf(pv, bW[j].y, a1));
                    a2 = fmaf(xv, bA[j].z, fmaf(pv, bW[j].z, a2));
                    a3 = fmaf(xv, bA[j].w, fmaf(pv, bW[j].w, a3));
                }
            }
        } else {
#pragma unroll 1
            for (int c = 0; c < 4; c++) {
                const int kb = k0 + c*16;
                float4 bA[16];
#pragma unroll
                for (int j = 0; j < 16; j++)
                    bA[j] = *(const float4*)(Uh + (kb + j)*U_ + u4);
#pragma unroll
                for (int j = 0; j < 16; j++) {
                    const float xv = xs[kb + j];
                    a0 = fmaf(xv, bA[j].x, a0);
                    a1 = fmaf(xv, bA[j].y, a1);
                    a2 = fmaf(xv, bA[j].z, a2);
                    a3 = fmaf(xv, bA[j].w, a3);
                }
            }
        }
        sred[tid] = make_float4(a0, a1, a2, a3);
        __syncthreads();

        if (kt == 0) {
            const float4 r0 = sred[ut], r1 = sred[64 + ut], r2 = sred[128 + ut], r3 = sred[192 + ut];
            float v[4] = { r0.x + r1.x + r2.x + r3.x, r0.y + r1.y + r2.y + r3.y,
                           r0.z + r1.z + r2.z + r3.z, r0.w + r1.w + r2.w + r3.w };
            if (slice == 0) {
#pragma unroll
                for (int j = 0; j < 4; j++) {
                    const float z = 1.f / (1.f + expf(-v[j]));
                    g_z [b*U_ + u4 + j] = z;
                    g_gz[b*U_ + u4 + j] = z * (1.f - z);
                }
            } else if (slice == 1) {
#pragma unroll
                for (int j = 0; j < 4; j++) {
                    const float r = 1.f / (1.f + expf(-v[j]));
                    g_r [b*U_ + u4 + j] = r;
                    g_gr[b*U_ + u4 + j] = r * (1.f - r);
                    g_gi[b*U_ + u4 + j] = ps[u4 + j] * r;
                }
            } else {
#pragma unroll
                for (int j = 0; j < 4; j++) g_ahx[b*U_ + u4 + j] = v[j];
            }
        }

        if (slice == 2) {
            float v0 = xs[tid]*xs[tid], v1 = ps[tid]*ps[tid], v2 = S[b*MAT + tid*(U_+1)];
#pragma unroll
            for (int off = 16; off > 0; off >>= 1) {
                v0 += __shfl_down_sync(0xFFFFFFFFu, v0, off);
                v1 += __shfl_down_sync(0xFFFFFFFFu, v1, off);
                v2 += __shfl_down_sync(0xFFFFFFFFu, v2, off);
            }
            if (lane == 0) { part[wd][0] = v0; part[wd][1] = v1; part[wd][2] = v2; }
            __syncthreads();
            if (tid == 0) {
                float s0 = 0.f, s1 = 0.f, s2 = 0.f;
#pragma unroll
                for (int w = 0; w < 8; w++) { s0 += part[w][0]; s1 += part[w][1]; s2 += part[w][2]; }
                g_nx[b] = s0; g_np[b] = s1; g_trS[b] = s2;
            }
        }
        return;
    }

    if (bid < 384) {                                   // ---- transW (192 blocks) ----
        __shared__ float tile[32][33];
        const int k = bid - 192;
        const int gidx = k >> 6, sub = k & 63;
        const float* W = (gidx == 0) ? Wz : (gidx == 1) ? Wr : Wh;
        __nv_bfloat16* Wt = (gidx == 0) ? g_Wtz : (gidx == 1) ? g_Wtr : g_Wth;
        const int m0 = (sub >> 3) * 32, i0 = (sub & 7) * 32;
        const int tx = tid & 31, ty = tid >> 5;
#pragma unroll
        for (int q = 0; q < 4; q++)
            tile[ty*4 + q][tx] = W[(m0 + ty*4 + q) * U_ + i0 + tx];
        __syncthreads();
#pragma unroll
        for (int q = 0; q < 4; q++)
            Wt[(i0 + ty*4 + q) * U_ + m0 + tx] = __float2bfloat16_rn(tile[tx][ty*4 + q]);
        return;
    }

    // ---- convS (2048 blocks) ----
    {
        const int base = ((bid - 384) * 256 + tid) * 8;
        float4 f0 = *(const float4*)(S + base);
        float4 f1 = *(const float4*)(S + base + 4);
        uint4 o;
        o.x = pack_bf2(f0.x, f0.y); o.y = pack_bf2(f0.z, f0.w);
        o.z = pack_bf2(f1.x, f1.y); o.w = pack_bf2(f1.z, f1.w);
        *(uint4*)(g_Sb + base) = o;
    }
}

// ---------------- fused T+Q kernel (gates2 folded into HP0 x==0 CTAs) --------
template<int HP>
__global__ void __launch_bounds__(512, 1)
tq_phase(const float* __restrict__ Sst, const float* __restrict__ prev,
         const float* __restrict__ ws0, const float* __restrict__ us0,
         const float* __restrict__ ws1, const float* __restrict__ us1,
         const float* __restrict__ Whf, float* __restrict__ mu_out,
         float* __restrict__ outp)
{
    extern __shared__ __nv_bfloat16 sm[];
    __shared__ float tpart[16];
    __shared__ float strg;

    const int tid = threadIdx.x, lane = tid & 31, wid = tid >> 5;
    const int mt   = blockIdx.x & 1;
    const int gate = (HP == 0) ? (blockIdx.x >> 1) : 0;
    const int b = blockIdx.y;
    const int i0 = mt * 128;

    // ---- folded gates pass 2 (HP0, blockIdx.x==0 only)
    if (HP == 0 && blockIdx.x == 0) {
        float* sf = (float*)sm;
        if (tid < 256) sf[tid] = g_gi[b*U_ + tid];
        __syncthreads();
        if (tid < 256) {
            const int kt = tid >> 6, ut = tid & 63;
            const int u4 = ut << 2, k0 = kt * 64;
            float a0 = 0.f, a1 = 0.f, a2 = 0.f, a3 = 0.f;
#pragma unroll 1
            for (int c = 0; c < 4; c++) {
                const int kb = k0 + c*16;
                float4 bW[16];
#pragma unroll
                for (int j = 0; j < 16; j++)
                    bW[j] = *(const float4*)(Whf + (kb + j)*U_ + u4);
#pragma unroll
                for (int j = 0; j < 16; j++) {
                    const float gv = sf[kb + j];
                    a0 = fmaf(gv, bW[j].x, a0);
                    a1 = fmaf(gv, bW[j].y, a1);
                    a2 = fmaf(gv, bW[j].z, a2);
                    a3 = fmaf(gv, bW[j].w, a3);
                }
            }
            ((float4*)(sf + 256))[tid] = make_float4(a0, a1, a2, a3);
        }
        __syncthreads();
        if (tid < 64) {
            const float4* sr4 = (const float4*)(sf + 256);
            const float4 r0 = sr4[tid], r1 = sr4[64 + tid], r2 = sr4[128 + tid], r3 = sr4[192 + tid];
            float v[4] = { r0.x + r1.x + r2.x + r3.x, r0.y + r1.y + r2.y + r3.y,
                           r0.z + r1.z + r2.z + r3.z, r0.w + r1.w + r2.w + r3.w };
            const int u4 = tid << 2;
#pragma unroll
            for (int j = 0; j < 4; j++) {
                const int u = u4 + j;
                const float ah = g_ahx[b*U_ + u] + v[j];
                const float h = tanhf(ah);
                g_h [b*U_ + u] = h;
                g_gh[b*U_ + u] = 1.f - h*h;
                const float z = g_z[b*U_ + u];
                mu_out[b*U_ + u] = z * prev[b*U_ + u] + (1.f - z) * h;
            }
        }
        if (tid < 256) {
            float v0 = sf[tid] * sf[tid];
#pragma unroll
            for (int off = 16; off > 0; off >>= 1)
                v0 += __shfl_down_sync(0xFFFFFFFFu, v0, off);
            if (lane == 0) tpart[wid] = v0;
        }
        __syncthreads();
        if (tid == 0) {
            float s = 0.f;
#pragma unroll
            for (int w = 0; w < 8; w++) s += tpart[w];
            g_ngin[b] = s;
        }
        __syncthreads();
    }

    float trg = 0.f;
    if (HP == 1) {
        float tv = (tid < U_) ? g_dg[b*U_ + tid] : 0.f;
#pragma unroll
        for (int off = 16; off > 0; off >>= 1)
            tv += __shfl_down_sync(0xFFFFFFFFu, tv, off);
        if (lane == 0) tpart[wid] = tv;
        __syncthreads();
        if (tid == 0) {
            float s = 0.f;
#pragma unroll
            for (int w = 0; w < 16; w++) s += tpart[w];
            strg = s;
        }
        __syncthreads();
        trg = strg;
    }

    const __nv_bfloat16* Wt = (HP == 1) ? g_Wth : (gate ? g_Wtr : g_Wtz);
    const __nv_bfloat16* Bmat = (HP == 1) ? (g_sgb + b*MAT) : (g_Sb + b*MAT);
    const __nv_bfloat16* Astrip = Wt + i0*U_;

    const uint32_t smb = smem_u32(sm);
    const uint32_t tsb = smb + (uint32_t)(TS_OFF * 2);

    const int lr = tid >> 3, lc = (tid & 7) << 3;

    auto load1 = [&](int st, int ch) {
        const uint32_t dA = smb + (uint32_t)((st*ST_ELE) * 2);
        const uint32_t dB = dA + (uint32_t)((128*SPAD) * 2);
        const int kb = ch * KC;
#pragma unroll
        for (int i = 0; i < 2; i++) {
            const int r = lr + i*64;
            cpa16(dA + (uint32_t)((r*SPAD + lc) * 2), Astrip + r*U_ + kb + lc);
        }
#pragma unroll
        for (int i = 0; i < 4; i++) {
            const int r = lr + i*64;
            cpa16(dB + (uint32_t)((r*SPAD + lc) * 2), Bmat + r*U_ + kb + lc);
        }
        CPA_COMMIT();
    };
    auto load2 = [&](int st, int ch) {
        const uint32_t dB = smb + (uint32_t)((st*ST_ELE) * 2);
        const int kb = ch * KC;
#pragma unroll
        for (int i = 0; i < 4; i++) {
            const int r = lr + i*64;
            cpa16(dB + (uint32_t)((r*SPAD + lc) * 2), Wt + r*U_ + kb + lc);
        }
        CPA_COMMIT();
    };

    const int warp_m = wid & 3, warp_n = wid >> 2;
    const int arow = (lane & 7) | (((lane >> 3) & 1) << 3);
    const int akof = (lane >> 4) << 3;
    const int bxrow = (lane & 7) + ((lane >> 4) << 3);
    const int bxkof = ((lane >> 3) & 1) << 3;
    const int rb = lane >> 2;
    const int cb = (lane & 3) << 1;
    const int jbase = warp_n * 64;

    float acc[2][8][4];

    // ===== step 1: T strip =====
#pragma unroll
    for (int ms = 0; ms < 2; ms++)
#pragma unroll
        for (int ns = 0; ns < 8; ns++)
#pragma unroll
            for (int q = 0; q < 4; q++) acc[ms][ns][q] = 0.f;

    load1(0, 0);
    load1(1, 1);
    for (int ch = 0; ch < NCH; ch++) {
        if (ch < NCH - 1) { CPA_WAIT1(); } else { CPA_WAIT0(); }
        __syncthreads();
        const int st = ch & 1;
        const uint32_t baseA = smb + (uint32_t)((st*ST_ELE) * 2);
        const uint32_t baseB = baseA + (uint32_t)((128*SPAD) * 2);
#pragma unroll
        for (int ks = 0; ks < KC/16; ks++) {
            const int k0 = ks * 16;
            uint32_t af[2][4];
#pragma unroll
            for (int ms = 0; ms < 2; ms++)
                ldsm_x4(af[ms], baseA + (uint32_t)(((warp_m*32 + ms*16 + arow)*SPAD + k0 + akof) * 2));
            uint32_t bf[8][2];
#pragma unroll
            for (int ns2 = 0; ns2 < 4; ns2++) {
                uint32_t q4[4];
                ldsm_x4(q4, baseB + (uint32_t)(((jbase + ns2*16 + bxrow)*SPAD + k0 + bxkof) * 2));
                bf[ns2*2][0]   = q4[0]; bf[ns2*2][1]   = q4[1];
                bf[ns2*2+1][0] = q4[2]; bf[ns2*2+1][1] = q4[3];
            }
#pragma unroll
            for (int ms = 0; ms < 2; ms++)
#pragma unroll
                for (int ns = 0; ns < 8; ns++)
                    mma16816(acc[ms][ns], af[ms], bf[ns]);
        }
        __syncthreads();
        if (ch + 2 < NCH) load1(st, ch + 2);
    }

#pragma unroll
    for (int ms = 0; ms < 2; ms++)
#pragma unroll
        for (int hh = 0; hh < 2; hh++) {
            const int rowl = warp_m*32 + ms*16 + hh*8 + rb;
#pragma unroll
            for (int ns = 0; ns < 8; ns++) {
                const int coll = jbase + ns*8 + cb;
                *(uint32_t*)((char*)sm + (TS_OFF + rowl*TPAD + coll)*2)
                    = pack_bf2(acc[ms][ns][hh*2], acc[ms][ns][hh*2 + 1]);
            }
        }
    __syncthreads();

    // ===== step 2: Q strip =====
#pragma unroll
    for (int ms = 0; ms < 2; ms++)
#pragma unroll
        for (int ns = 0; ns < 8; ns++)
#pragma unroll
            for (int q = 0; q < 4; q++) acc[ms][ns][q] = 0.f;

    load2(0, 0);
    load2(1, 1);
    for (int ch = 0; ch < NCH; ch++) {
        if (ch < NCH - 1) { CPA_WAIT1(); } else { CPA_WAIT0(); }
        __syncthreads();
        const int st = ch & 1;
        const uint32_t baseB = smb + (uint32_t)((st*ST_ELE) * 2);
        const int kb = ch * KC;
#pragma unroll
        for (int ks = 0; ks < KC/16; ks++) {
            const int k0 = ks * 16;
            uint32_t af[2][4];
#pragma unroll
            for (int ms = 0; ms < 2; ms++)
                ldsm_x4(af[ms], tsb + (uint32_t)(((warp_m*32 + ms*16 + arow)*TPAD + kb + k0 + akof) * 2));
            uint32_t bf[8][2];
#pragma unroll
            for (int ns2 = 0; ns2 < 4; ns2++) {
                uint32_t q4[4];
                ldsm_x4(q4, baseB + (uint32_t)(((jbase + ns2*16 + bxrow)*SPAD + k0 + bxkof) * 2));
                bf[ns2*2][0]   = q4[0]; bf[ns2*2][1]   = q4[1];
                bf[ns2*2+1][0] = q4[2]; bf[ns2*2+1][1] = q4[3];
            }
#pragma unroll
            for (int ms = 0; ms < 2; ms++)
#pragma unroll
                for (int ns = 0; ns < 8; ns++)
                    mma16816(acc[ms][ns], af[ms], bf[ns]);
        }
        __syncthreads();
        if (ch + 2 < NCH) load2(st, ch + 2);
    }

    // ===== fused epilogues =====
    if (HP == 0 && gate == 0) {                    // Sigma_out_z: bf16 + fp32 diag
        const float nx = g_nx[b], sc = g_np[b] + g_trS[b];
        float2 gzj[8];
#pragma unroll
        for (int ns = 0; ns < 8; ns++)
            gzj[ns] = *(const float2*)(g_gz + b*U_ + jbase + ns*8 + cb);
#pragma unroll
        for (int ms = 0; ms < 2; ms++)
#pragma unroll
            for (int hh = 0; hh < 2; hh++) {
                const int row = i0 + warp_m*32 + ms*16 + hh*8 + rb;
                const float dadd = sc * splus(ws0[row]) + nx * splus(us0[row]);
                const float gzi = g_gz[b*U_ + row];
                __nv_bfloat16* dstr = g_Szb + b*MAT + row*U_;
#pragma unroll
                for (int ns = 0; ns < 8; ns++) {
                    const int colg = jbase + ns*8 + cb;
                    float v0 = acc[ms][ns][hh*2], v1 = acc[ms][ns][hh*2 + 1];
                    if (colg == row)     v0 += dadd;
                    if (colg + 1 == row) v1 += dadd;
                    const float o0 = v0 * gzi * gzj[ns].x;
                    const float o1 = v1 * gzi * gzj[ns].y;
                    if (colg == row)     g_dz[b*U_ + row] = o0;
                    if (colg + 1 == row) g_dz[b*U_ + row] = o1;
                    *(uint32_t*)(dstr + colg) = pack_bf2(o0, o1);
                }
            }
    }
    else if (HP == 0) {                            // sigma_g (bf16 + fp32 diag)
        const float nx = g_nx[b], sc = g_np[b] + g_trS[b];
        float2 grj[8], rj[8], pj[8];
#pragma unroll
        for (int ns = 0; ns < 8; ns++) {
            const int cg = jbase + ns*8 + cb;
            grj[ns] = *(const float2*)(g_gr + b*U_ + cg);
            rj[ns]  = *(const float2*)(g_r  + b*U_ + cg);
            pj[ns]  = *(const float2*)(prev + b*U_ + cg);
        }
#pragma unroll
        for (int ms = 0; ms < 2; ms++)
#pragma unroll
            for (int hh = 0; hh < 2; hh++) {
                const int row = i0 + warp_m*32 + ms*16 + hh*8 + rb;
                const float dadd = sc * splus(ws1[row]) + nx * splus(us1[row]);
                const float gri = g_gr[b*U_ + row];
                const float ri  = g_r [b*U_ + row];
                const float pi  = prev[b*U_ + row];
                const float* Srow = Sst + b*MAT + row*U_;
                __nv_bfloat16* dstr = g_sgb + b*MAT + row*U_;
#pragma unroll
                for (int ns = 0; ns < 8; ns++) {
                    const int colg = jbase + ns*8 + cb;
                    float v0 = acc[ms][ns][hh*2], v1 = acc[ms][ns][hh*2 + 1];
                    if (colg == row)     v0 += dadd;
                    if (colg + 1 == row) v1 += dadd;
                    const float2 Sv = *(const float2*)(Srow + colg);
                    const float sr0 = v0 * gri * grj[ns].x;
                    const float sr1 = v1 * gri * grj[ns].y;
                    const float res0 = Sv.x*sr0 + pi*pj[ns].x*sr0 + ri*rj[ns].x*Sv.x;
                    const float res1 = Sv.y*sr1 + pi*pj[ns].y*sr1 + ri*rj[ns].y*Sv.y;
                    if (colg == row)     g_dg[b*U_ + row] = res0;
                    if (colg + 1 == row) g_dg[b*U_ + row] = res1;
                    *(uint32_t*)(dstr + colg) = pack_bf2(res0, res1);
                }
            }
    }
    else {                                         // HP 1: final Sigma_out
        const float nx = g_nx[b], sc = g_ngin[b] + trg;
        float2 ghj[8], zj[8], hj[8], pj[8];
#pragma unroll
        for (int ns = 0; ns < 8; ns++) {
            const int cg = jbase + ns*8 + cb;
            ghj[ns] = *(const float2*)(g_gh + b*U_ + cg);
            zj[ns]  = *(const float2*)(g_z  + b*U_ + cg);
            hj[ns]  = *(const float2*)(g_h  + b*U_ + cg);
            pj[ns]  = *(const float2*)(prev + b*U_ + cg);
        }
#pragma unroll
        for (int ms = 0; ms < 2; ms++)
#pragma unroll
            for (int hh = 0; hh < 2; hh++) {
                const int row = i0 + warp_m*32 + ms*16 + hh*8 + rb;
                const float dadd = sc * splus(ws0[row]) + nx * splus(us0[row]);
                const float ghi = g_gh[b*U_ + row];
                const float zi  = g_z [b*U_ + row];
                const float hi  = g_h [b*U_ + row];
                const float pi  = prev[b*U_ + row];
                const float dzi = g_dz[b*U_ + row];
                const __nv_bfloat16* Szrow = g_Szb + b*MAT + row*U_;
                const float* Srow  = Sst  + b*MAT + row*U_;
                float* dstr = outp + b*MAT + row*U_;
#pragma unroll
                for (int ns = 0; ns < 8; ns++) {
                    const int colg = jbase + ns*8 + cb;
                    float v0 = acc[ms][ns][hh*2], v1 = acc[ms][ns][hh*2 + 1];
                    if (colg == row)     v0 += dadd;
                    if (colg + 1 == row) v1 += dadd;
                    const float2 Szv = unpack_bf2(*(const uint32_t*)(Szrow + colg));
                    const float2 Ssv = *(const float2*)(Srow + colg);
                    float2 o;
#pragma unroll
                    for (int e = 0; e < 2; e++) {
                        const int j = colg + e;
                        const float q  = (e == 0) ? v0 : v1;
                        float Sz = (e == 0) ? Szv.x : Szv.y;
                        if (j == row) Sz = dzi;
                        const float Ss = (e == 0) ? Ssv.x : Ssv.y;
                        const float zjv = (e == 0) ? zj[ns].x : zj[ns].y;
                        const float hjv = (e == 0) ? hj[ns].x : hj[ns].y;
                        const float pjv = (e == 0) ? pj[ns].x : pj[ns].y;
                        const float Sh = q * ghi * ((e == 0) ? ghj[ns].x : ghj[ns].y);
                        float oo = Sz*Ss + zi*zjv*Ss + pi*pjv*Sz
                                 + Sz*Sh + (1.f - zi)*(1.f - zjv)*Sh + hi*hjv*Sz
                                 - Sz*(pi*hjv + hi*pjv);
                        const unsigned bits = __float_as_uint(oo);
                        if (((bits >> 23) & 255u) == 255u) oo = 0.f;
                        if (j == row) oo = fabsf(oo);
                        (e == 0 ? o.x : o.y) = oo;
                    }
                    *(float2*)(dstr + colg) = o;
                }
            }
    }
}

// ---------------- launch ----------------
extern "C" void kernel_launch(void* const* d_in, const int* in_sizes, int n_in,
                              void* d_out, int out_size)
{
    const float* x    = (const float*)d_in[0];
    const float* prev = (const float*)d_in[1];
    const float* S    = (const float*)d_in[2];
    const float* Uz   = (const float*)d_in[3];
    const float* uzs  = (const float*)d_in[4];
    const float* Wz   = (const float*)d_in[5];
    const float* wzs  = (const float*)d_in[6];
    const float* Ur   = (const float*)d_in[7];
    const float* urs  = (const float*)d_in[8];
    const float* Wr   = (const float*)d_in[9];
    const float* wrs  = (const float*)d_in[10];
    const float* Uh   = (const float*)d_in[11];
    const float* uhs  = (const float*)d_in[12];
    const float* Wh   = (const float*)d_in[13];
    const float* whs  = (const float*)d_in[14];
    float* out = (float*)d_out;

    cudaFuncSetAttribute(tq_phase<0>, cudaFuncAttributeMaxDynamicSharedMemorySize, SM_DYN);
    cudaFuncSetAttribute(tq_phase<1>, cudaFuncAttributeMaxDynamicSharedMemorySize, SM_DYN);

    prep_kernel<<<2432, 256>>>(S, Wz, Wr, Wh, x, prev, Uz, Ur, Uh);

    float* sig_out = out + B_*U_;
    tq_phase<0><<<dim3(4, 64), 512, SM_DYN>>>(S, prev, wzs, uzs, wrs, urs, Wh, out, sig_out);
    tq_phase<1><<<dim3(2, 64), 512, SM_DYN>>>(S, prev, whs, uhs, whs, uhs, Wh, out, sig_out);
}

// round 17
// speedup vs baseline: 1.0251x; 1.0040x over previous
#include <cuda_runtime.h>
#include <cuda_bf16.h>
#include <math.h>
#include <stdint.h>

#define B_  64
#define U_  256
#define MAT (U_*U_)
#define BM_ (B_*MAT)
#define KC   64
#define NCH  (U_/KC)
#define SPAD 72                    // chunk row pad (bf16)
#define TPAD 264                   // T-strip row pad (bf16)
#define ST_ELE ((128 + 256) * SPAD)
#define TS_OFF (2*ST_ELE)
#define SM_ELE (TS_OFF + 128*TPAD)
#define SM_DYN (SM_ELE*2)

// ---------------- scratch (__device__ globals; device-side access only) ----------------
__device__ __align__(16) __nv_bfloat16 g_Sb [BM_];
__device__ __align__(16) __nv_bfloat16 g_Wtz[MAT];
__device__ __align__(16) __nv_bfloat16 g_Wtr[MAT];
__device__ __align__(16) __nv_bfloat16 g_Wth[MAT];
__device__ __align__(16) __nv_bfloat16 g_sgb[BM_];
__device__ __align__(16) __nv_bfloat16 g_Szb[BM_];   // Sigma_out_z bf16 off-diag
__device__ float g_dz[B_*U_];                        // fp32 diag of Sigma_out_z
__device__ float g_dg[B_*U_];                        // fp32 diag of sigma_g
__device__ float g_dS[B_*U_];                        // fp32 diag of Sigma_state
__device__ float g_z [B_*U_], g_gz[B_*U_], g_r [B_*U_], g_gr[B_*U_];
__device__ float g_h [B_*U_], g_gh[B_*U_];
__device__ float g_gi[B_*U_], g_ahx[B_*U_];
__device__ float g_nx[B_], g_np[B_], g_ngin[B_], g_trS[B_];

__device__ __forceinline__ float splus(float x) { return log1pf(expf(x)); }

__device__ __forceinline__ uint32_t smem_u32(const void* p) {
    uint32_t a;
    asm("{ .reg .u64 t; cvta.to.shared.u64 t, %1; cvt.u32.u64 %0, t; }" : "=r"(a) : "l"(p));
    return a;
}
__device__ __forceinline__ uint32_t pack_bf2(float lo, float hi) {
    __nv_bfloat162 v = __floats2bfloat162_rn(lo, hi);
    return *(uint32_t*)&v;
}
__device__ __forceinline__ float2 unpack_bf2(uint32_t u) {
    return __bfloat1622float2(*(__nv_bfloat162*)&u);
}
__device__ __forceinline__ void ldsm_x4(uint32_t* r, uint32_t addr) {
    asm volatile("ldmatrix.sync.aligned.m8n8.x4.shared.b16 {%0,%1,%2,%3}, [%4];"
        : "=r"(r[0]), "=r"(r[1]), "=r"(r[2]), "=r"(r[3]) : "r"(addr));
}
__device__ __forceinline__ void mma16816(float* c, const uint32_t* a, const uint32_t* b) {
    asm volatile("mma.sync.aligned.m16n8k16.row.col.f32.bf16.bf16.f32 "
        "{%0,%1,%2,%3}, {%4,%5,%6,%7}, {%8,%9}, {%0,%1,%2,%3};"
        : "+f"(c[0]), "+f"(c[1]), "+f"(c[2]), "+f"(c[3])
        : "r"(a[0]), "r"(a[1]), "r"(a[2]), "r"(a[3]), "r"(b[0]), "r"(b[1]));
}
__device__ __forceinline__ void cpa16(uint32_t dst, const void* src) {
    asm volatile("cp.async.cg.shared.global [%0], [%1], 16;" :: "r"(dst), "l"(src));
}
#define CPA_COMMIT() asm volatile("cp.async.commit_group;" ::: "memory")
#define CPA_WAIT1()  asm volatile("cp.async.wait_group 1;" ::: "memory")
#define CPA_WAIT0()  asm volatile("cp.async.wait_group 0;" ::: "memory")

// ---------------- fused prep: gates pass 1 | transW | convS ----------------
__global__ void __launch_bounds__(256)
prep_kernel(const float* __restrict__ S,
            const float* __restrict__ Wz, const float* __restrict__ Wr,
            const float* __restrict__ Wh,
            const float* __restrict__ x, const float* __restrict__ prev,
            const float* __restrict__ Uz, const float* __restrict__ Ur,
            const float* __restrict__ Uh)
{
    const int bid = blockIdx.x, tid = threadIdx.x;

    if (bid < 192) {        // ---- gates pass 1 (slice 0 = z, 1 = r, 2 = h_x + scalars) ----
        __shared__ float xs[U_], ps[U_];
        __shared__ float4 sred[256];
        __shared__ float part[8][3];
        const int slice = bid / 64;
        const int b = bid & 63;
        const int lane = tid & 31, wd = tid >> 5;
        xs[tid] = x[b*U_ + tid];
        ps[tid] = prev[b*U_ + tid];
        __syncthreads();

        const int kt = tid >> 6, ut = tid & 63;
        const int u4 = ut << 2;
        const int k0 = kt * 64;
        float a0 = 0.f, a1 = 0.f, a2 = 0.f, a3 = 0.f;

        if (slice < 2) {
            const float* Ug = slice ? Ur : Uz;
            const float* Wg = slice ? Wr : Wz;
#pragma unroll 1
            for (int c = 0; c < 8; c++) {
                const int kb = k0 + c*8;
                float4 bA[8], bW[8];
#pragma unroll
                for (int j = 0; j < 8; j++) {
                    bA[j] = *(const float4*)(Ug + (kb + j)*U_ + u4);
                    bW[j] = *(const float4*)(Wg + (kb + j)*U_ + u4);
                }
#pragma unroll
                for (int j = 0; j < 8; j++) {
                    const float xv = xs[kb + j], pv = ps[kb + j];
                    a0 = fmaf(xv, bA[j].x, fmaf(pv, bW[j].x, a0));
                    a1 = fmaf(xv, bA[j].y, fmaf(pv, bW[j].y, a1));
                    a2 = fmaf(xv, bA[j].z, fmaf(pv, bW[j].z, a2));
                    a3 = fmaf(xv, bA[j].w, fmaf(pv, bW[j].w, a3));
                }
            }
        } else {
#pragma unroll 1
            for (int c = 0; c < 4; c++) {
                const int kb = k0 + c*16;
                float4 bA[16];
#pragma unroll
                for (int j = 0; j < 16; j++)
                    bA[j] = *(const float4*)(Uh + (kb + j)*U_ + u4);
#pragma unroll
                for (int j = 0; j < 16; j++) {
                    const float xv = xs[kb + j];
                    a0 = fmaf(xv, bA[j].x, a0);
                    a1 = fmaf(xv, bA[j].y, a1);
                    a2 = fmaf(xv, bA[j].z, a2);
                    a3 = fmaf(xv, bA[j].w, a3);
                }
            }
        }
        sred[tid] = make_float4(a0, a1, a2, a3);
        __syncthreads();

        if (kt == 0) {
            const float4 r0 = sred[ut], r1 = sred[64 + ut], r2 = sred[128 + ut], r3 = sred[192 + ut];
            float v[4] = { r0.x + r1.x + r2.x + r3.x, r0.y + r1.y + r2.y + r3.y,
                           r0.z + r1.z + r2.z + r3.z, r0.w + r1.w + r2.w + r3.w };
            if (slice == 0) {
#pragma unroll
                for (int j = 0; j < 4; j++) {
                    const float z = 1.f / (1.f + expf(-v[j]));
                    g_z [b*U_ + u4 + j] = z;
                    g_gz[b*U_ + u4 + j] = z * (1.f - z);
                }
            } else if (slice == 1) {
#pragma unroll
                for (int j = 0; j < 4; j++) {
                    const float r = 1.f / (1.f + expf(-v[j]));
                    g_r [b*U_ + u4 + j] = r;
                    g_gr[b*U_ + u4 + j] = r * (1.f - r);
                    g_gi[b*U_ + u4 + j] = ps[u4 + j] * r;
                }
            } else {
#pragma unroll
                for (int j = 0; j < 4; j++) g_ahx[b*U_ + u4 + j] = v[j];
            }
        }

        if (slice == 2) {
            const float dS = S[b*MAT + tid*(U_+1)];
            g_dS[b*U_ + tid] = dS;                       // fp32 S diagonal for epilogues
            float v0 = xs[tid]*xs[tid], v1 = ps[tid]*ps[tid], v2 = dS;
#pragma unroll
            for (int off = 16; off > 0; off >>= 1) {
                v0 += __shfl_down_sync(0xFFFFFFFFu, v0, off);
                v1 += __shfl_down_sync(0xFFFFFFFFu, v1, off);
                v2 += __shfl_down_sync(0xFFFFFFFFu, v2, off);
            }
            if (lane == 0) { part[wd][0] = v0; part[wd][1] = v1; part[wd][2] = v2; }
            __syncthreads();
            if (tid == 0) {
                float s0 = 0.f, s1 = 0.f, s2 = 0.f;
#pragma unroll
                for (int w = 0; w < 8; w++) { s0 += part[w][0]; s1 += part[w][1]; s2 += part[w][2]; }
                g_nx[b] = s0; g_np[b] = s1; g_trS[b] = s2;
            }
        }
        return;
    }

    if (bid < 384) {                                   // ---- transW (192 blocks) ----
        __shared__ float tile[32][33];
        const int k = bid - 192;
        const int gidx = k >> 6, sub = k & 63;
        const float* W = (gidx == 0) ? Wz : (gidx == 1) ? Wr : Wh;
        __nv_bfloat16* Wt = (gidx == 0) ? g_Wtz : (gidx == 1) ? g_Wtr : g_Wth;
        const int m0 = (sub >> 3) * 32, i0 = (sub & 7) * 32;
        const int tx = tid & 31, ty = tid >> 5;
#pragma unroll
        for (int q = 0; q < 4; q++)
            tile[ty*4 + q][tx] = W[(m0 + ty*4 + q) * U_ + i0 + tx];
        __syncthreads();
#pragma unroll
        for (int q = 0; q < 4; q++)
            Wt[(i0 + ty*4 + q) * U_ + m0 + tx] = __float2bfloat16_rn(tile[tx][ty*4 + q]);
        return;
    }

    // ---- convS (2048 blocks) ----
    {
        const int base = ((bid - 384) * 256 + tid) * 8;
        float4 f0 = *(const float4*)(S + base);
        float4 f1 = *(const float4*)(S + base + 4);
        uint4 o;
        o.x = pack_bf2(f0.x, f0.y); o.y = pack_bf2(f0.z, f0.w);
        o.z = pack_bf2(f1.x, f1.y); o.w = pack_bf2(f1.z, f1.w);
        *(uint4*)(g_Sb + base) = o;
    }
}

// ---------------- fused T+Q kernel (gates2 folded into HP0 x==0 CTAs) --------
template<int HP>
__global__ void __launch_bounds__(512, 1)
tq_phase(const float* __restrict__ prev,
         const float* __restrict__ ws0, const float* __restrict__ us0,
         const float* __restrict__ ws1, const float* __restrict__ us1,
         const float* __restrict__ Whf, float* __restrict__ mu_out,
         float* __restrict__ outp)
{
    extern __shared__ __nv_bfloat16 sm[];
    __shared__ float tpart[16];
    __shared__ float strg;

    const int tid = threadIdx.x, lane = tid & 31, wid = tid >> 5;
    const int mt   = blockIdx.x & 1;
    const int gate = (HP == 0) ? (blockIdx.x >> 1) : 0;
    const int b = blockIdx.y;
    const int i0 = mt * 128;

    // ---- folded gates pass 2 (HP0, blockIdx.x==0 only)
    if (HP == 0 && blockIdx.x == 0) {
        float* sf = (float*)sm;
        if (tid < 256) sf[tid] = g_gi[b*U_ + tid];
        __syncthreads();
        if (tid < 256) {
            const int kt = tid >> 6, ut = tid & 63;
            const int u4 = ut << 2, k0 = kt * 64;
            float a0 = 0.f, a1 = 0.f, a2 = 0.f, a3 = 0.f;
#pragma unroll 1
            for (int c = 0; c < 4; c++) {
                const int kb = k0 + c*16;
                float4 bW[16];
#pragma unroll
                for (int j = 0; j < 16; j++)
                    bW[j] = *(const float4*)(Whf + (kb + j)*U_ + u4);
#pragma unroll
                for (int j = 0; j < 16; j++) {
                    const float gv = sf[kb + j];
                    a0 = fmaf(gv, bW[j].x, a0);
                    a1 = fmaf(gv, bW[j].y, a1);
                    a2 = fmaf(gv, bW[j].z, a2);
                    a3 = fmaf(gv, bW[j].w, a3);
                }
            }
            ((float4*)(sf + 256))[tid] = make_float4(a0, a1, a2, a3);
        }
        __syncthreads();
        if (tid < 64) {
            const float4* sr4 = (const float4*)(sf + 256);
            const float4 r0 = sr4[tid], r1 = sr4[64 + tid], r2 = sr4[128 + tid], r3 = sr4[192 + tid];
            float v[4] = { r0.x + r1.x + r2.x + r3.x, r0.y + r1.y + r2.y + r3.y,
                           r0.z + r1.z + r2.z + r3.z, r0.w + r1.w + r2.w + r3.w };
            const int u4 = tid << 2;
#pragma unroll
            for (int j = 0; j < 4; j++) {
                const int u = u4 + j;
                const float ah = g_ahx[b*U_ + u] + v[j];
                const float h = tanhf(ah);
                g_h [b*U_ + u] = h;
                g_gh[b*U_ + u] = 1.f - h*h;
                const float z = g_z[b*U_ + u];
                mu_out[b*U_ + u] = z * prev[b*U_ + u] + (1.f - z) * h;
            }
        }
        if (tid < 256) {
            float v0 = sf[tid] * sf[tid];
#pragma unroll
            for (int off = 16; off > 0; off >>= 1)
                v0 += __shfl_down_sync(0xFFFFFFFFu, v0, off);
            if (lane == 0) tpart[wid] = v0;
        }
        __syncthreads();
        if (tid == 0) {
            float s = 0.f;
#pragma unroll
            for (int w = 0; w < 8; w++) s += tpart[w];
            g_ngin[b] = s;
        }
        __syncthreads();
    }

    float trg = 0.f;
    if (HP == 1) {
        float tv = (tid < U_) ? g_dg[b*U_ + tid] : 0.f;
#pragma unroll
        for (int off = 16; off > 0; off >>= 1)
            tv += __shfl_down_sync(0xFFFFFFFFu, tv, off);
        if (lane == 0) tpart[wid] = tv;
        __syncthreads();
        if (tid == 0) {
            float s = 0.f;
#pragma unroll
            for (int w = 0; w < 16; w++) s += tpart[w];
            strg = s;
        }
        __syncthreads();
        trg = strg;
    }

    const __nv_bfloat16* Wt = (HP == 1) ? g_Wth : (gate ? g_Wtr : g_Wtz);
    const __nv_bfloat16* Bmat = (HP == 1) ? (g_sgb + b*MAT) : (g_Sb + b*MAT);
    const __nv_bfloat16* Astrip = Wt + i0*U_;

    const uint32_t smb = smem_u32(sm);
    const uint32_t tsb = smb + (uint32_t)(TS_OFF * 2);

    const int lr = tid >> 3, lc = (tid & 7) << 3;

    auto load1 = [&](int st, int ch) {
        const uint32_t dA = smb + (uint32_t)((st*ST_ELE) * 2);
        const uint32_t dB = dA + (uint32_t)((128*SPAD) * 2);
        const int kb = ch * KC;
#pragma unroll
        for (int i = 0; i < 2; i++) {
            const int r = lr + i*64;
            cpa16(dA + (uint32_t)((r*SPAD + lc) * 2), Astrip + r*U_ + kb + lc);
        }
#pragma unroll
        for (int i = 0; i < 4; i++) {
            const int r = lr + i*64;
            cpa16(dB + (uint32_t)((r*SPAD + lc) * 2), Bmat + r*U_ + kb + lc);
        }
        CPA_COMMIT();
    };
    auto load2 = [&](int st, int ch) {
        const uint32_t dB = smb + (uint32_t)((st*ST_ELE) * 2);
        const int kb = ch * KC;
#pragma unroll
        for (int i = 0; i < 4; i++) {
            const int r = lr + i*64;
            cpa16(dB + (uint32_t)((r*SPAD + lc) * 2), Wt + r*U_ + kb + lc);
        }
        CPA_COMMIT();
    };

    const int warp_m = wid & 3, warp_n = wid >> 2;
    const int arow = (lane & 7) | (((lane >> 3) & 1) << 3);
    const int akof = (lane >> 4) << 3;
    const int bxrow = (lane & 7) + ((lane >> 4) << 3);
    const int bxkof = ((lane >> 3) & 1) << 3;
    const int rb = lane >> 2;
    const int cb = (lane & 3) << 1;
    const int jbase = warp_n * 64;

    float acc[2][8][4];

    // ===== step 1: T strip =====
#pragma unroll
    for (int ms = 0; ms < 2; ms++)
#pragma unroll
        for (int ns = 0; ns < 8; ns++)
#pragma unroll
            for (int q = 0; q < 4; q++) acc[ms][ns][q] = 0.f;

    load1(0, 0);
    load1(1, 1);
    for (int ch = 0; ch < NCH; ch++) {
        if (ch < NCH - 1) { CPA_WAIT1(); } else { CPA_WAIT0(); }
        __syncthreads();
        const int st = ch & 1;
        const uint32_t baseA = smb + (uint32_t)((st*ST_ELE) * 2);
        const uint32_t baseB = baseA + (uint32_t)((128*SPAD) * 2);
#pragma unroll
        for (int ks = 0; ks < KC/16; ks++) {
            const int k0 = ks * 16;
            uint32_t af[2][4];
#pragma unroll
            for (int ms = 0; ms < 2; ms++)
                ldsm_x4(af[ms], baseA + (uint32_t)(((warp_m*32 + ms*16 + arow)*SPAD + k0 + akof) * 2));
            uint32_t bf[8][2];
#pragma unroll
            for (int ns2 = 0; ns2 < 4; ns2++) {
                uint32_t q4[4];
                ldsm_x4(q4, baseB + (uint32_t)(((jbase + ns2*16 + bxrow)*SPAD + k0 + bxkof) * 2));
                bf[ns2*2][0]   = q4[0]; bf[ns2*2][1]   = q4[1];
                bf[ns2*2+1][0] = q4[2]; bf[ns2*2+1][1] = q4[3];
            }
#pragma unroll
            for (int ms = 0; ms < 2; ms++)
#pragma unroll
                for (int ns = 0; ns < 8; ns++)
                    mma16816(acc[ms][ns], af[ms], bf[ns]);
        }
        __syncthreads();
        if (ch + 2 < NCH) load1(st, ch + 2);
    }

#pragma unroll
    for (int ms = 0; ms < 2; ms++)
#pragma unroll
        for (int hh = 0; hh < 2; hh++) {
            const int rowl = warp_m*32 + ms*16 + hh*8 + rb;
#pragma unroll
            for (int ns = 0; ns < 8; ns++) {
                const int coll = jbase + ns*8 + cb;
                *(uint32_t*)((char*)sm + (TS_OFF + rowl*TPAD + coll)*2)
                    = pack_bf2(acc[ms][ns][hh*2], acc[ms][ns][hh*2 + 1]);
            }
        }
    __syncthreads();

    // ===== step 2: Q strip =====
#pragma unroll
    for (int ms = 0; ms < 2; ms++)
#pragma unroll
        for (int ns = 0; ns < 8; ns++)
#pragma unroll
            for (int q = 0; q < 4; q++) acc[ms][ns][q] = 0.f;

    load2(0, 0);
    load2(1, 1);
    for (int ch = 0; ch < NCH; ch++) {
        if (ch < NCH - 1) { CPA_WAIT1(); } else { CPA_WAIT0(); }
        __syncthreads();
        const int st = ch & 1;
        const uint32_t baseB = smb + (uint32_t)((st*ST_ELE) * 2);
        const int kb = ch * KC;
#pragma unroll
        for (int ks = 0; ks < KC/16; ks++) {
            const int k0 = ks * 16;
            uint32_t af[2][4];
#pragma unroll
            for (int ms = 0; ms < 2; ms++)
                ldsm_x4(af[ms], tsb + (uint32_t)(((warp_m*32 + ms*16 + arow)*TPAD + kb + k0 + akof) * 2));
            uint32_t bf[8][2];
#pragma unroll
            for (int ns2 = 0; ns2 < 4; ns2++) {
                uint32_t q4[4];
                ldsm_x4(q4, baseB + (uint32_t)(((jbase + ns2*16 + bxrow)*SPAD + k0 + bxkof) * 2));
                bf[ns2*2][0]   = q4[0]; bf[ns2*2][1]   = q4[1];
                bf[ns2*2+1][0] = q4[2]; bf[ns2*2+1][1] = q4[3];
            }
#pragma unroll
            for (int ms = 0; ms < 2; ms++)
#pragma unroll
                for (int ns = 0; ns < 8; ns++)
                    mma16816(acc[ms][ns], af[ms], bf[ns]);
        }
        __syncthreads();
        if (ch + 2 < NCH) load2(st, ch + 2);
    }

    // ===== fused epilogues =====
    if (HP == 0 && gate == 0) {                    // Sigma_out_z: bf16 + fp32 diag
        const float nx = g_nx[b], sc = g_np[b] + g_trS[b];
        float2 gzj[8];
#pragma unroll
        for (int ns = 0; ns < 8; ns++)
            gzj[ns] = *(const float2*)(g_gz + b*U_ + jbase + ns*8 + cb);
#pragma unroll
        for (int ms = 0; ms < 2; ms++)
#pragma unroll
            for (int hh = 0; hh < 2; hh++) {
                const int row = i0 + warp_m*32 + ms*16 + hh*8 + rb;
                const float dadd = sc * splus(ws0[row]) + nx * splus(us0[row]);
                const float gzi = g_gz[b*U_ + row];
                __nv_bfloat16* dstr = g_Szb + b*MAT + row*U_;
#pragma unroll
                for (int ns = 0; ns < 8; ns++) {
                    const int colg = jbase + ns*8 + cb;
                    float v0 = acc[ms][ns][hh*2], v1 = acc[ms][ns][hh*2 + 1];
                    if (colg == row)     v0 += dadd;
                    if (colg + 1 == row) v1 += dadd;
                    const float o0 = v0 * gzi * gzj[ns].x;
                    const float o1 = v1 * gzi * gzj[ns].y;
                    if (colg == row)     g_dz[b*U_ + row] = o0;
                    if (colg + 1 == row) g_dz[b*U_ + row] = o1;
                    *(uint32_t*)(dstr + colg) = pack_bf2(o0, o1);
                }
            }
    }
    else if (HP == 0) {                            // sigma_g (bf16 + fp32 diag; S via bf16+fp32 diag)
        const float nx = g_nx[b], sc = g_np[b] + g_trS[b];
        float2 grj[8], rj[8], pj[8];
#pragma unroll
        for (int ns = 0; ns < 8; ns++) {
            const int cg = jbase + ns*8 + cb;
            grj[ns] = *(const float2*)(g_gr + b*U_ + cg);
            rj[ns]  = *(const float2*)(g_r  + b*U_ + cg);
            pj[ns]  = *(const float2*)(prev + b*U_ + cg);
        }
#pragma unroll
        for (int ms = 0; ms < 2; ms++)
#pragma unroll
            for (int hh = 0; hh < 2; hh++) {
                const int row = i0 + warp_m*32 + ms*16 + hh*8 + rb;
                const float dadd = sc * splus(ws1[row]) + nx * splus(us1[row]);
                const float gri = g_gr[b*U_ + row];
                const float ri  = g_r [b*U_ + row];
                const float pi  = prev[b*U_ + row];
                const float dSi = g_dS[b*U_ + row];
                const __nv_bfloat16* Sbrow = g_Sb + b*MAT + row*U_;
                __nv_bfloat16* dstr = g_sgb + b*MAT + row*U_;
#pragma unroll
                for (int ns = 0; ns < 8; ns++) {
                    const int colg = jbase + ns*8 + cb;
                    float v0 = acc[ms][ns][hh*2], v1 = acc[ms][ns][hh*2 + 1];
                    if (colg == row)     v0 += dadd;
                    if (colg + 1 == row) v1 += dadd;
                    float2 Sv = unpack_bf2(*(const uint32_t*)(Sbrow + colg));
                    if (colg == row)     Sv.x = dSi;
                    if (colg + 1 == row) Sv.y = dSi;
                    const float sr0 = v0 * gri * grj[ns].x;
                    const float sr1 = v1 * gri * grj[ns].y;
                    const float res0 = Sv.x*sr0 + pi*pj[ns].x*sr0 + ri*rj[ns].x*Sv.x;
                    const float res1 = Sv.y*sr1 + pi*pj[ns].y*sr1 + ri*rj[ns].y*Sv.y;
                    if (colg == row)     g_dg[b*U_ + row] = res0;
                    if (colg + 1 == row) g_dg[b*U_ + row] = res1;
                    *(uint32_t*)(dstr + colg) = pack_bf2(res0, res1);
                }
            }
    }
    else {                                         // HP 1: final Sigma_out (S via bf16+fp32 diag)
        const float nx = g_nx[b], sc = g_ngin[b] + trg;
        float2 ghj[8], zj[8], hj[8], pj[8];
#pragma unroll
        for (int ns = 0; ns < 8; ns++) {
            const int cg = jbase + ns*8 + cb;
            ghj[ns] = *(const float2*)(g_gh + b*U_ + cg);
            zj[ns]  = *(const float2*)(g_z  + b*U_ + cg);
            hj[ns]  = *(const float2*)(g_h  + b*U_ + cg);
            pj[ns]  = *(const float2*)(prev + b*U_ + cg);
        }
#pragma unroll
        for (int ms = 0; ms < 2; ms++)
#pragma unroll
            for (int hh = 0; hh < 2; hh++) {
                const int row = i0 + warp_m*32 + ms*16 + hh*8 + rb;
                const float dadd = sc * splus(ws0[row]) + nx * splus(us0[row]);
                const float ghi = g_gh[b*U_ + row];
                const float zi  = g_z [b*U_ + row];
                const float hi  = g_h [b*U_ + row];
                const float pi  = prev[b*U_ + row];
                const float dzi = g_dz[b*U_ + row];
                const float dSi = g_dS[b*U_ + row];
                const __nv_bfloat16* Szrow = g_Szb + b*MAT + row*U_;
                const __nv_bfloat16* Sbrow = g_Sb  + b*MAT + row*U_;
                float* dstr = outp + b*MAT + row*U_;
#pragma unroll
                for (int ns = 0; ns < 8; ns++) {
                    const int colg = jbase + ns*8 + cb;
                    float v0 = acc[ms][ns][hh*2], v1 = acc[ms][ns][hh*2 + 1];
                    if (colg == row)     v0 += dadd;
                    if (colg + 1 == row) v1 += dadd;
                    const float2 Szv = unpack_bf2(*(const uint32_t*)(Szrow + colg));
                    const float2 Ssv = unpack_bf2(*(const uint32_t*)(Sbrow + colg));
                    float2 o;
#pragma unroll
                    for (int e = 0; e < 2; e++) {
                        const int j = colg + e;
                        const float q  = (e == 0) ? v0 : v1;
                        float Sz = (e == 0) ? Szv.x : Szv.y;
                        float Ss = (e == 0) ? Ssv.x : Ssv.y;
                        if (j == row) { Sz = dzi; Ss = dSi; }
                        const float zjv = (e == 0) ? zj[ns].x : zj[ns].y;
                        const float hjv = (e == 0) ? hj[ns].x : hj[ns].y;
                        const float pjv = (e == 0) ? pj[ns].x : pj[ns].y;
                        const float Sh = q * ghi * ((e == 0) ? ghj[ns].x : ghj[ns].y);
                        float oo = Sz*Ss + zi*zjv*Ss + pi*pjv*Sz
                                 + Sz*Sh + (1.f - zi)*(1.f - zjv)*Sh + hi*hjv*Sz
                                 - Sz*(pi*hjv + hi*pjv);
                        const unsigned bits = __float_as_uint(oo);
                        if (((bits >> 23) & 255u) == 255u) oo = 0.f;
                        if (j == row) oo = fabsf(oo);
                        (e == 0 ? o.x : o.y) = oo;
                    }
                    *(float2*)(dstr + colg) = o;
                }
            }
    }
}

// ---------------- launch ----------------
extern "C" void kernel_launch(void* const* d_in, const int* in_sizes, int n_in,
                              void* d_out, int out_size)
{
    const float* x    = (const float*)d_in[0];
    const float* prev = (const float*)d_in[1];
    const float* S    = (const float*)d_in[2];
    const float* Uz   = (const float*)d_in[3];
    const float* uzs  = (const float*)d_in[4];
    const float* Wz   = (const float*)d_in[5];
    const float* wzs  = (const float*)d_in[6];
    const float* Ur   = (const float*)d_in[7];
    const float* urs  = (const float*)d_in[8];
    const float* Wr   = (const float*)d_in[9];
    const float* wrs  = (const float*)d_in[10];
    const float* Uh   = (const float*)d_in[11];
    const float* uhs  = (const float*)d_in[12];
    const float* Wh   = (const float*)d_in[13];
    const float* whs  = (const float*)d_in[14];
    float* out = (float*)d_out;

    cudaFuncSetAttribute(tq_phase<0>, cudaFuncAttributeMaxDynamicSharedMemorySize, SM_DYN);
    cudaFuncSetAttribute(tq_phase<1>, cudaFuncAttributeMaxDynamicSharedMemorySize, SM_DYN);

    prep_kernel<<<2432, 256>>>(S, Wz, Wr, Wh, x, prev, Uz, Ur, Uh);

    float* sig_out = out + B_*U_;
    tq_phase<0><<<dim3(4, 64), 512, SM_DYN>>>(prev, wzs, uzs, wrs, urs, Wh, out, sig_out);
    tq_phase<1><<<dim3(2, 64), 512, SM_DYN>>>(prev, whs, uhs, whs, uhs, Wh, out, sig_out);
}